// round 14
// baseline (speedup 1.0000x reference)
#include <cuda_runtime.h>
#include <cuda_fp16.h>
#include <math.h>

#define BB 8
#define IN_N 8
#define JJ 8
#define SS 187
#define FF 64
#define OO 64
#define CC 67
#define KK 15
#define SF (SS*FF)
#define NOUT (BB*JJ*SS*OO)
#define ECHUNK 1496    // SF/8

// ---------------- device scratch ----------------
__device__ float  g_pmax[148];
__device__ float  g_epart[BB*IN_N*8*JJ];
__device__ float  g_gate[BB*IN_N*JJ];
__device__ __half g_act [BB*IN_N*JJ*SF];   // fp16
__device__ float  g_comb[BB*JJ*SS*FF];
__device__ float  g_xp  [BB*JJ*SS*OO];
__device__ float  g_rs  [BB*IN_N*SS];
__device__ float  g_ss  [BB*IN_N*SS];
__device__ float  g_P   [BB*4*SS*SS];

// ---------------- f32x2 helpers ----------------
__device__ __forceinline__ unsigned long long pack2(float a) {
    unsigned long long r;
    asm("mov.b64 %0, {%1, %1};" : "=l"(r) : "f"(a));
    return r;
}
__device__ __forceinline__ unsigned long long packab(float a, float b) {
    unsigned long long r;
    asm("mov.b64 %0, {%1, %2};" : "=l"(r) : "f"(a), "f"(b));
    return r;
}
__device__ __forceinline__ void ffma2(unsigned long long& d, unsigned long long a,
                                      unsigned long long b) {
    asm("fma.rn.f32x2 %0, %1, %2, %0;" : "+l"(d) : "l"(a), "l"(b));
}
__device__ __forceinline__ void unpack2(unsigned long long v, float& lo, float& hi) {
    asm("mov.b64 {%0, %1}, %2;" : "=f"(lo), "=f"(hi) : "l"(v));
}

// ---------------- K1: maxabs partials (critical path, 148 blocks) ----------------
__global__ void k_prep(const float* __restrict__ x, int n) {
    __shared__ float sred[256];
    float m = 0.f;
    for (int i = blockIdx.x * 256 + threadIdx.x; i < n; i += 148 * 256)
        m = fmaxf(m, fabsf(x[i]));
    sred[threadIdx.x] = m;
    __syncthreads();
    for (int st = 128; st > 0; st >>= 1) {
        if (threadIdx.x < st) sred[threadIdx.x] = fmaxf(sred[threadIdx.x], sred[threadIdx.x + st]);
        __syncthreads();
    }
    if (threadIdx.x == 0) g_pmax[blockIdx.x] = sred[0];
}

// ---------------- K1b: proj row stats (side stream) ----------------
__global__ void k_stats(const float* __restrict__ proj) {
    int bi = blockIdx.x;
    int w = threadIdx.x >> 5, lane = threadIdx.x & 31;
    const float* pb = proj + (size_t)bi*SS*FF;
    for (int s = w; s < SS; s += 8) {
        float a = pb[(size_t)s*FF + lane];
        float c = pb[(size_t)s*FF + lane + 32];
        float sm = a + c, sq = a*a + c*c;
#pragma unroll
        for (int o = 16; o > 0; o >>= 1) {
            sm += __shfl_xor_sync(0xffffffffu, sm, o);
            sq += __shfl_xor_sync(0xffffffffu, sq, o);
        }
        if (lane == 0) { g_rs[bi*SS + s] = sm; g_ss[bi*SS + s] = sq; }
    }
}

__device__ __forceinline__ float reduce_maxv(int tid, float* s_pm) {
    if (tid < 32) {
        float m = 0.f;
        for (int t = tid; t < 148; t += 32) m = fmaxf(m, g_pmax[t]);
#pragma unroll
        for (int o = 16; o > 0; o >>= 1) m = fmaxf(m, __shfl_xor_sync(0xffffffffu, m, o));
        if (tid == 0) *s_pm = m;
    }
    __syncthreads();
    return *s_pm;
}

__device__ __forceinline__ void spline_basis(float x, float inv_maxv_sc, float invh,
                                             float bas[4], int& c0) {
    float xn = x * inv_maxv_sc;
    xn = fminf(fmaxf(xn, -0.99f), 0.99f);
    float u = (xn + 1.0f) * invh;
    float fl = floorf(u);
    float t = u - fl;
    int fli = (int)fl;
    c0 = fli - 1;
    float omt = 1.0f - t;
    float t3 = t*t*t;
    float o3 = omt*omt*omt;
    bas[0] = (fli >= 1) ? o3 * (1.0f/6.0f) : 0.f;
    bas[1] = (2.0f-t)*(2.0f-t)*(2.0f-t)*(1.0f/6.0f) - o3*(4.0f/6.0f);
    bas[2] = (1.0f+t)*(1.0f+t)*(1.0f+t)*(1.0f/6.0f) - t3*(4.0f/6.0f);
    bas[3] = (fli <= 64) ? t3 * (1.0f/6.0f) : 0.f;
}

// ---------------- K2: spline -> act(fp16) + energy (f32x2 pairs over j) ----------------
#define SWST 12
__global__ void k_spline(const float* __restrict__ x_in,
                         const float* __restrict__ sw,
                         const float* __restrict__ omiga) {
    int bi = blockIdx.x, i = bi % IN_N, cy = blockIdx.y;
    __shared__ float s_swT[CC*SWST];
    __shared__ float s_om[JJ];
    __shared__ float s_red[8][9];
    __shared__ float s_pm;
    int tid = threadIdx.x;
    float maxv = reduce_maxv(tid, &s_pm) + 1e-8f;
    for (int t = tid; t < CC*JJ; t += blockDim.x) {
        int c = t >> 3, j = t & 7;
        s_swT[c*SWST + j] = sw[(i*JJ + j)*CC + c];
    }
    if (tid < JJ) s_om[tid] = fabsf(omiga[i*JJ + tid]);
    __syncthreads();

    float inv_maxv_sc = 0.95f / maxv;
    const float invh = (float)(CC - 1) * 0.5f;

    unsigned long long om2[4];
#pragma unroll
    for (int jj = 0; jj < 4; jj++) om2[jj] = packab(s_om[2*jj], s_om[2*jj + 1]);

    unsigned long long accp[4];
#pragma unroll
    for (int jj = 0; jj < 4; jj++) accp[jj] = 0ull;

    const float* xb   = x_in + (size_t)bi * SF;
    __half*      actb = g_act + (size_t)bi * JJ * SF;
    int p0 = (cy * ECHUNK) >> 1, p1 = min(SF, cy * ECHUNK + ECHUNK) >> 1;
    for (int p = p0 + tid; p < p1; p += blockDim.x) {
        int idx = 2 * p;
        float2 x2 = *(const float2*)(xb + idx);
        unsigned long long ap[4], aq[4];
        unsigned long long px = pack2(x2.x), py = pack2(x2.y);
#pragma unroll
        for (int jj = 0; jj < 4; jj++) { ap[jj] = 0ull; aq[jj] = 0ull; }
#pragma unroll
        for (int jj = 0; jj < 4; jj++) { ffma2(ap[jj], om2[jj], px); ffma2(aq[jj], om2[jj], py); }
        {
            float bas[4]; int c0;
            spline_basis(x2.x, inv_maxv_sc, invh, bas, c0);
            int r0[4] = { max(c0,0), c0+1, c0+2, min(c0+3, CC-1) };
#pragma unroll
            for (int k = 0; k < 4; k++) {
                const ulonglong2* pr = (const ulonglong2*)(s_swT + r0[k]*SWST);
                ulonglong2 lo = pr[0], hi = pr[1];
                unsigned long long bk = pack2(bas[k]);
                ffma2(ap[0], bk, lo.x); ffma2(ap[1], bk, lo.y);
                ffma2(ap[2], bk, hi.x); ffma2(ap[3], bk, hi.y);
            }
        }
        {
            float bas[4]; int c0;
            spline_basis(x2.y, inv_maxv_sc, invh, bas, c0);
            int r0[4] = { max(c0,0), c0+1, c0+2, min(c0+3, CC-1) };
#pragma unroll
            for (int k = 0; k < 4; k++) {
                const ulonglong2* pr = (const ulonglong2*)(s_swT + r0[k]*SWST);
                ulonglong2 lo = pr[0], hi = pr[1];
                unsigned long long bk = pack2(bas[k]);
                ffma2(aq[0], bk, lo.x); ffma2(aq[1], bk, lo.y);
                ffma2(aq[2], bk, hi.x); ffma2(aq[3], bk, hi.y);
            }
        }
#pragma unroll
        for (int jj = 0; jj < 4; jj++) {
            float e0lo, e0hi, e1lo, e1hi;
            unpack2(ap[jj], e0lo, e0hi);
            unpack2(aq[jj], e1lo, e1hi);
            *(__half2*)(actb + (size_t)(2*jj    )*SF + idx) = __floats2half2_rn(e0lo, e1lo);
            *(__half2*)(actb + (size_t)(2*jj + 1)*SF + idx) = __floats2half2_rn(e0hi, e1hi);
            ffma2(accp[jj], ap[jj], ap[jj]);
            ffma2(accp[jj], aq[jj], aq[jj]);
        }
    }
    float acc[JJ];
#pragma unroll
    for (int jj = 0; jj < 4; jj++) unpack2(accp[jj], acc[2*jj], acc[2*jj + 1]);
    int lane = tid & 31, wid = tid >> 5;
#pragma unroll
    for (int j = 0; j < JJ; j++) {
#pragma unroll
        for (int o = 16; o > 0; o >>= 1) acc[j] += __shfl_down_sync(0xffffffffu, acc[j], o);
        if (lane == 0) s_red[wid][j] = acc[j];
    }
    __syncthreads();
    if (tid < JJ) {
        float e = 0.f;
#pragma unroll
        for (int w = 0; w < 8; w++) e += s_red[w][tid];
        g_epart[(bi*8 + cy)*JJ + tid] = e;
    }
}

// ---------------- K3: fused combined + LN + W2 GEMV (2 rows per warp, 768 blocks) ----
__global__ void k_cxp(const float* __restrict__ W2,
                      const float* __restrict__ bparam,
                      const float* __restrict__ lnsc,
                      const float* __restrict__ lnbi,
                      const float* __restrict__ tau,
                      const float* __restrict__ temp,
                      float* __restrict__ xp_out) {
    int bj = blockIdx.x;
    int b = bj >> 3, j = bj & 7;
    __shared__ float W2s[FF*OO];
    __shared__ float s_sc[FF], s_bi[FF];
    __shared__ float s_mask[IN_N];
    __shared__ float xlnw[16][FF];
    int tid = threadIdx.x;

    for (int t = tid; t < FF*OO/4; t += blockDim.x)
        ((float4*)W2s)[t] = ((const float4*)(W2 + (size_t)j*FF*OO))[t];
    if (tid < FF) {
        s_sc[tid] = lnsc[j*FF + tid];
        s_bi[tid] = lnbi[j*FF + tid];
    }
    if (tid < IN_N) {
        int i = tid, bi = b*IN_N + i;
        float e = 0.f;
#pragma unroll
        for (int c = 0; c < 8; c++) e += g_epart[(bi*8 + c)*JJ + j];
        e *= (1.0f / (float)SF);
        float sq = sqrtf(e + 1e-8f);
        float ta = fabsf(tau[i*JJ + j]);
        float tv = fabsf(temp[0]) * sqrtf((float)SS / 256.0f) + 1e-4f;
        float mk = 1.0f / (1.0f + expf(-(sq - ta) / tv));
        s_mask[tid] = mk;
        if (blockIdx.y == 0) g_gate[bi*JJ + j] = (sq / (ta + 1e-8f)) * mk;
    }
    __syncthreads();

    int w = tid >> 5, lane = tid & 31;
    int s0 = blockIdx.y * 16;
    const float* bpj = bparam + (size_t)j*SS*OO;
    float* cmbb = g_comb + (size_t)bj*SF;
    float* xpb  = g_xp   + (size_t)bj*SS*OO;
    float* xob  = xp_out ? (xp_out + (size_t)bj*SS*OO) : nullptr;

    float m[8];
#pragma unroll
    for (int i = 0; i < 8; i++) m[i] = s_mask[i];

    int rbase = 2 * w;
#pragma unroll
    for (int r = 0; r < 2; r++) {
        int lr = rbase + r;
        int s = s0 + lr;
        if (s < SS) {
            float c0 = 0.f, c1 = 0.f;
#pragma unroll
            for (int i = 0; i < IN_N; i++) {
                const __half2* ap = (const __half2*)(g_act + ((size_t)(b*IN_N + i)*JJ + j)*SF
                                                     + (size_t)s*FF + 2*lane);
                float2 f2 = __half22float2(*ap);
                c0 += m[i] * f2.x;
                c1 += m[i] * f2.y;
            }
            *(float2*)(cmbb + (size_t)s*FF + 2*lane) = make_float2(c0, c1);
            float sm = c0 + c1, sq = c0*c0 + c1*c1;
#pragma unroll
            for (int o = 16; o > 0; o >>= 1) {
                sm += __shfl_xor_sync(0xffffffffu, sm, o);
                sq += __shfl_xor_sync(0xffffffffu, sq, o);
            }
            float mean = sm * (1.0f/64.0f);
            float var  = sq * (1.0f/64.0f) - mean*mean;
            float rstd = rsqrtf(var + 1e-5f);
            xlnw[lr][2*lane]     = (c0 - mean)*rstd*s_sc[2*lane]     + s_bi[2*lane];
            xlnw[lr][2*lane + 1] = (c1 - mean)*rstd*s_sc[2*lane + 1] + s_bi[2*lane + 1];
        } else {
            xlnw[lr][2*lane] = 0.f;
            xlnw[lr][2*lane + 1] = 0.f;
        }
    }
    __syncwarp();

    unsigned long long acc[2];
#pragma unroll
    for (int r = 0; r < 2; r++) {
        int s = s0 + rbase + r;
        acc[r] = (s < SS) ? *(const unsigned long long*)(bpj + (size_t)s*OO + 2*lane) : 0ull;
    }
#pragma unroll 8
    for (int ff = 0; ff < FF; ff++) {
        unsigned long long w2v = *(const unsigned long long*)&W2s[ff*OO + 2*lane];
        ffma2(acc[0], pack2(xlnw[rbase + 0][ff]), w2v);
        ffma2(acc[1], pack2(xlnw[rbase + 1][ff]), w2v);
    }
#pragma unroll
    for (int r = 0; r < 2; r++) {
        int s = s0 + rbase + r;
        if (s < SS) {
            *(unsigned long long*)(xpb + (size_t)s*OO + 2*lane) = acc[r];
            if (xob) *(unsigned long long*)(xob + (size_t)s*OO + 2*lane) = acc[r];
        }
    }
}

// ---------------- K4: P_m = projK @ projQ^T ----------------
__global__ void k_pgemm(const float* __restrict__ proj) {
    int bm = blockIdx.z;
    int b = bm >> 2, m = bm & 3;
    const float* A  = proj + ((size_t)(b*IN_N + 2*m    )*SS)*FF;
    const float* Bm = proj + ((size_t)(b*IN_N + 2*m + 1)*SS)*FF;
    float*       Cm = g_P + (size_t)bm*SS*SS;
    int m0 = blockIdx.y * 64, n0 = blockIdx.x * 64;

    __shared__ float As[16][64];
    __shared__ float Bs[16][64];
    int tid = threadIdx.x;
    int lr  = tid >> 2;
    int lc  = (tid & 3) * 4;
    int ty  = tid >> 4, tx = tid & 15;

    unsigned long long acc[4][2];
#pragma unroll
    for (int r = 0; r < 4; r++) { acc[r][0] = 0ull; acc[r][1] = 0ull; }

    for (int k0 = 0; k0 < FF; k0 += 16) {
        int row = m0 + lr;
        float4 va = (row < SS) ? *(const float4*)(A + (size_t)row*FF + k0 + lc)
                               : make_float4(0,0,0,0);
        As[lc+0][lr] = va.x; As[lc+1][lr] = va.y; As[lc+2][lr] = va.z; As[lc+3][lr] = va.w;
        int rowb = n0 + lr;
        float4 vb = (rowb < SS) ? *(const float4*)(Bm + (size_t)rowb*FF + k0 + lc)
                                : make_float4(0,0,0,0);
        Bs[lc+0][lr] = vb.x; Bs[lc+1][lr] = vb.y; Bs[lc+2][lr] = vb.z; Bs[lc+3][lr] = vb.w;
        __syncthreads();
#pragma unroll
        for (int k = 0; k < 16; k++) {
            float4 a4 = *(const float4*)&As[k][ty*4];
            ulonglong2 b2 = *(const ulonglong2*)&Bs[k][tx*4];
            unsigned long long p0 = pack2(a4.x), p1 = pack2(a4.y);
            unsigned long long p2 = pack2(a4.z), p3 = pack2(a4.w);
            ffma2(acc[0][0], p0, b2.x); ffma2(acc[0][1], p0, b2.y);
            ffma2(acc[1][0], p1, b2.x); ffma2(acc[1][1], p1, b2.y);
            ffma2(acc[2][0], p2, b2.x); ffma2(acc[2][1], p2, b2.y);
            ffma2(acc[3][0], p3, b2.x); ffma2(acc[3][1], p3, b2.y);
        }
        __syncthreads();
    }
#pragma unroll
    for (int r = 0; r < 4; r++) {
        int sRow = m0 + ty*4 + r;
        if (sRow >= SS) continue;
        float c0, c1, c2, c3;
        unpack2(acc[r][0], c0, c1);
        unpack2(acc[r][1], c2, c3);
        int tCol = n0 + tx*4;
        float* dst = Cm + (size_t)sRow*SS + tCol;
        if (tCol + 3 < SS) { dst[0]=c0; dst[1]=c1; dst[2]=c2; dst[3]=c3; }
        else {
            if (tCol+0 < SS) dst[0]=c0;
            if (tCol+1 < SS) dst[1]=c1;
            if (tCol+2 < SS) dst[2]=c2;
            if (tCol+3 < SS) dst[3]=c3;
        }
    }
}

// ---------------- K5: fused raw-reconstruct + softmax + attn GEMM + conv + residual ----
#define AST_LD 65
__global__ void k_attn(const float* __restrict__ w3,
                       const float* __restrict__ alpha,
                       const float* __restrict__ beta,
                       const float* __restrict__ theta,
                       const float* __restrict__ gamma,
                       const float* __restrict__ temp,
                       float* __restrict__ outp) {
    extern __shared__ float smem[];
    float* Ast = smem;
    float* Bxs = Ast + 192*AST_LD;
    float* w3s = Bxs + 192*64;
    __shared__ float qr_sh[SS], qmr_sh[SS];
    __shared__ float km_sh[64], As_sh[64];
    __shared__ float a_sh[4];

    int bj = blockIdx.y;
    int j  = bj & 7, b = bj >> 3;
    int m0 = blockIdx.x * 64;
    int tid = threadIdx.x;

    const float* Bx = g_xp  + (size_t)bj*SS*OO;
    const float* Cb = g_comb + (size_t)bj*SS*FF;
    float*       Ob = outp + (size_t)bj*SS*OO;

    float tv = fabsf(temp[0]) * sqrtf((float)SS / 256.0f) + 1e-4f;
    float inv_scale = 1.0f / (16.0f * tv);

    for (int t = tid; t < SS*OO/4; t += 256)
        ((float4*)Bxs)[t] = ((const float4*)Bx)[t];
    for (int t = SS*OO + tid; t < 192*64; t += 256) Bxs[t] = 0.f;
    for (int t = tid; t < OO*KK; t += 256) w3s[t] = w3[(size_t)j*OO*KK + t];

    if (tid < 4) {
        float gK = g_gate[(b*IN_N + 2*tid    )*JJ + j];
        float gQ = g_gate[(b*IN_N + 2*tid + 1)*JJ + j];
        a_sh[tid] = gK * gQ;
    }
    if (tid < SS) {
        float qm = 0.f, qs = 0.f;
#pragma unroll
        for (int m = 0; m < 4; m++) {
            int bi = b*IN_N + 2*m + 1;
            float g = g_gate[bi*JJ + j];
            qm += g * g_rs[bi*SS + tid];
            qs += g * g * g_ss[bi*SS + tid];
        }
        qm *= (1.0f/256.0f); qs *= (1.0f/256.0f);
        float qr = rsqrtf(qs - qm*qm + 1e-5f);
        qr_sh[tid]  = qr;
        qmr_sh[tid] = 256.0f * qm * qr;
    }
    if (tid >= 192) {
        int r = tid - 192;
        int s = m0 + r;
        if (s < SS) {
            float km = 0.f, ks = 0.f;
#pragma unroll
            for (int m = 0; m < 4; m++) {
                int bi = b*IN_N + 2*m;
                float g = g_gate[bi*JJ + j];
                km += g * g_rs[bi*SS + s];
                ks += g * g * g_ss[bi*SS + s];
            }
            km *= (1.0f/256.0f); ks *= (1.0f/256.0f);
            float kr = rsqrtf(ks - km*km + 1e-5f);
            km_sh[r] = km;
            As_sh[r] = inv_scale * kr;
        }
    }
    __syncthreads();

    float a0 = a_sh[0], a1 = a_sh[1], a2 = a_sh[2], a3 = a_sh[3];
    const float* Pb = g_P + (size_t)(b*4)*SS*SS;

    int w = tid >> 5, lane = tid & 31;
    for (int r = w; r < 64; r += 8) {
        int s = m0 + r;
        if (s < SS) {
            float km = km_sh[r], Asc = As_sh[r];
            const float* P0 = Pb + (size_t)0*SS*SS + (size_t)s*SS;
            const float* P1 = Pb + (size_t)1*SS*SS + (size_t)s*SS;
            const float* P2 = Pb + (size_t)2*SS*SS + (size_t)s*SS;
            const float* P3 = Pb + (size_t)3*SS*SS + (size_t)s*SS;
            float v[6];
            float mx = -3.0e38f;
#pragma unroll
            for (int u = 0; u < 6; u++) {
                int t = lane + 32*u;
                if (t < SS) {
                    float G = a0*P0[t] + a1*P1[t] + a2*P2[t] + a3*P3[t];
                    v[u] = Asc * (qr_sh[t]*G - km*qmr_sh[t]);
                } else v[u] = -3.0e38f;
                mx = fmaxf(mx, v[u]);
            }
#pragma unroll
            for (int o = 16; o > 0; o >>= 1) mx = fmaxf(mx, __shfl_xor_sync(0xffffffffu, mx, o));
            float sum = 0.f;
#pragma unroll
            for (int u = 0; u < 6; u++) {
                int t = lane + 32*u;
                v[u] = (t < SS) ? expf(v[u] - mx) : 0.f;
                sum += v[u];
            }
#pragma unroll
            for (int o = 16; o > 0; o >>= 1) sum += __shfl_xor_sync(0xffffffffu, sum, o);
            float inv = 1.0f / sum;
#pragma unroll
            for (int u = 0; u < 6; u++) Ast[(lane + 32*u)*AST_LD + r] = v[u] * inv;
        } else {
#pragma unroll
            for (int u = 0; u < 6; u++) Ast[(lane + 32*u)*AST_LD + r] = 0.f;
        }
    }
    __syncthreads();

    int ty = tid >> 4, tx = tid & 15;
    unsigned long long acc[4][2];
#pragma unroll
    for (int r = 0; r < 4; r++) { acc[r][0] = 0ull; acc[r][1] = 0ull; }

#pragma unroll 4
    for (int k = 0; k < 192; k++) {
        const float* ap = Ast + k*AST_LD + ty*4;
        float b0 = ap[0], b1 = ap[1], b2v = ap[2], b3 = ap[3];
        ulonglong2 bp = *(const ulonglong2*)(Bxs + k*64 + tx*4);
        unsigned long long p0 = pack2(b0), p1 = pack2(b1);
        unsigned long long p2 = pack2(b2v), p3 = pack2(b3);
        ffma2(acc[0][0], p0, bp.x); ffma2(acc[0][1], p0, bp.y);
        ffma2(acc[1][0], p1, bp.x); ffma2(acc[1][1], p1, bp.y);
        ffma2(acc[2][0], p2, bp.x); ffma2(acc[2][1], p2, bp.y);
        ffma2(acc[3][0], p3, bp.x); ffma2(acc[3][1], p3, bp.y);
    }

    float al = fabsf(alpha[j]), be = fabsf(beta[j]);
    float th = fabsf(theta[j]), ga = gamma[j];

    float outv[4][4];
#pragma unroll
    for (int c = 0; c < 4; c++) {
        int o = tx*4 + c;
        float w3v[KK];
#pragma unroll
        for (int k = 0; k < KK; k++) w3v[k] = w3s[o*KK + k];
        float xv[18];
        int base = m0 + ty*4 - 7;
#pragma unroll
        for (int t = 0; t < 18; t++) {
            int si = base + t;
            xv[t] = (si >= 0 && si < 192) ? Bxs[si*64 + o] : 0.f;
        }
#pragma unroll
        for (int r = 0; r < 4; r++) {
            float cv = 0.f;
#pragma unroll
            for (int k = 0; k < KK; k++) cv += xv[r + k] * w3v[k];
            float glo, ghi;
            unpack2(acc[r][c >> 1], glo, ghi);
            float gval = (c & 1) ? ghi : glo;
            outv[r][c] = be*gval + al*xv[r + 7] + th*cv;
        }
    }
#pragma unroll
    for (int r = 0; r < 4; r++) {
        int s = m0 + ty*4 + r;
        if (s >= SS) continue;
#pragma unroll
        for (int c = 0; c < 4; c++) {
            int o = tx*4 + c;
            Ob[(size_t)s*OO + o] = outv[r][c] + ga*Cb[(size_t)s*FF + o];
        }
    }
}

// ---------------- launch ----------------
extern "C" void kernel_launch(void* const* d_in, const int* in_sizes, int n_in,
                              void* d_out, int out_size) {
    const float* x_in   = (const float*)d_in[0];
    const float* proj   = (const float*)d_in[1];
    const float* sw     = (const float*)d_in[2];
    const float* tau    = (const float*)d_in[3];
    const float* temp   = (const float*)d_in[4];
    const float* omiga  = (const float*)d_in[5];
    const float* W2     = (const float*)d_in[6];
    const float* bparam = (const float*)d_in[7];
    const float* lnsc   = (const float*)d_in[8];
    const float* lnbi   = (const float*)d_in[9];
    const float* alpha  = (const float*)d_in[10];
    const float* beta   = (const float*)d_in[11];
    const float* theta  = (const float*)d_in[12];
    const float* gamma  = (const float*)d_in[13];
    const float* w3     = (const float*)d_in[14];
    float* outp = (float*)d_out;
    float* xp_out = (out_size >= 2 * NOUT) ? (outp + NOUT) : nullptr;

    static cudaStream_t s2 = nullptr;
    static cudaEvent_t evA = nullptr, evB = nullptr;
    if (!s2) {
        cudaStreamCreateWithFlags(&s2, cudaStreamNonBlocking);
        cudaEventCreateWithFlags(&evA, cudaEventDisableTiming);
        cudaEventCreateWithFlags(&evB, cudaEventDisableTiming);
    }

    const int attn_smem = (192*AST_LD + 192*64 + OO*KK) * sizeof(float);
    cudaFuncSetAttribute(k_attn, cudaFuncAttributeMaxDynamicSharedMemorySize, attn_smem);

    // side stream: pgemm + proj stats (depend only on proj; join before attn)
    cudaEventRecord(evA, 0);
    cudaStreamWaitEvent(s2, evA, 0);
    k_pgemm<<<dim3(3, 3, BB*4), 256, 0, s2>>>(proj);
    k_stats<<<BB*IN_N, 256, 0, s2>>>(proj);
    cudaEventRecord(evB, s2);

    k_prep  <<<148, 256>>>(x_in, BB*IN_N*SS*FF);
    k_spline<<<dim3(BB*IN_N, 8), 256>>>(x_in, sw, omiga);
    k_cxp   <<<dim3(BB*JJ, 12), 256>>>(W2, bparam, lnsc, lnbi, tau, temp, xp_out);

    cudaStreamWaitEvent(0, evB, 0);
    k_attn  <<<dim3(3, BB*JJ), 256, attn_smem>>>(w3, alpha, beta, theta, gamma, temp, outp);
}

// round 17
// speedup vs baseline: 1.4249x; 1.4249x over previous
#include <cuda_runtime.h>
#include <cuda_fp16.h>
#include <math.h>

#define BB 8
#define IN_N 8
#define JJ 8
#define SS 187
#define FF 64
#define OO 64
#define CC 67
#define KK 15
#define SF (SS*FF)
#define NOUT (BB*JJ*SS*OO)
#define NCHUNK 16
#define ECHUNK 748     // SF/16

// ---------------- device scratch ----------------
__device__ float  g_pmax[148];
__device__ float  g_epart[BB*IN_N*NCHUNK*JJ];
__device__ float  g_gate[BB*IN_N*JJ];
__device__ __half g_act [BB*IN_N*JJ*SF];   // fp16
__device__ float  g_comb[BB*JJ*SS*FF];
__device__ float  g_xp  [BB*JJ*SS*OO];
__device__ float  g_rs  [BB*IN_N*SS];
__device__ float  g_ss  [BB*IN_N*SS];
__device__ float  g_P   [BB*4*SS*SS];

// ---------------- f32x2 helpers ----------------
__device__ __forceinline__ unsigned long long pack2(float a) {
    unsigned long long r;
    asm("mov.b64 %0, {%1, %1};" : "=l"(r) : "f"(a));
    return r;
}
__device__ __forceinline__ unsigned long long packab(float a, float b) {
    unsigned long long r;
    asm("mov.b64 %0, {%1, %2};" : "=l"(r) : "f"(a), "f"(b));
    return r;
}
__device__ __forceinline__ void ffma2(unsigned long long& d, unsigned long long a,
                                      unsigned long long b) {
    asm("fma.rn.f32x2 %0, %1, %2, %0;" : "+l"(d) : "l"(a), "l"(b));
}
__device__ __forceinline__ void unpack2(unsigned long long v, float& lo, float& hi) {
    asm("mov.b64 {%0, %1}, %2;" : "=f"(lo), "=f"(hi) : "l"(v));
}

// ---------------- K1: fused maxabs partials + proj row stats ----------------
__global__ void k_prep(const float* __restrict__ x, int n, const float* __restrict__ proj) {
    if (blockIdx.x < 148) {
        __shared__ float sred[256];
        float m = 0.f;
        for (int i = blockIdx.x * 256 + threadIdx.x; i < n; i += 148 * 256)
            m = fmaxf(m, fabsf(x[i]));
        sred[threadIdx.x] = m;
        __syncthreads();
        for (int st = 128; st > 0; st >>= 1) {
            if (threadIdx.x < st) sred[threadIdx.x] = fmaxf(sred[threadIdx.x], sred[threadIdx.x + st]);
            __syncthreads();
        }
        if (threadIdx.x == 0) g_pmax[blockIdx.x] = sred[0];
    } else {
        int bi = blockIdx.x - 148;
        int w = threadIdx.x >> 5, lane = threadIdx.x & 31;
        const float* pb = proj + (size_t)bi*SS*FF;
        for (int s = w; s < SS; s += 8) {
            float a = pb[(size_t)s*FF + lane];
            float c = pb[(size_t)s*FF + lane + 32];
            float sm = a + c, sq = a*a + c*c;
#pragma unroll
            for (int o = 16; o > 0; o >>= 1) {
                sm += __shfl_xor_sync(0xffffffffu, sm, o);
                sq += __shfl_xor_sync(0xffffffffu, sq, o);
            }
            if (lane == 0) { g_rs[bi*SS + s] = sm; g_ss[bi*SS + s] = sq; }
        }
    }
}

__device__ __forceinline__ float reduce_maxv(int tid, float* s_pm) {
    if (tid < 32) {
        float m = 0.f;
        for (int t = tid; t < 148; t += 32) m = fmaxf(m, g_pmax[t]);
#pragma unroll
        for (int o = 16; o > 0; o >>= 1) m = fmaxf(m, __shfl_xor_sync(0xffffffffu, m, o));
        if (tid == 0) *s_pm = m;
    }
    __syncthreads();
    return *s_pm;
}

__device__ __forceinline__ void spline_basis(float x, float inv_maxv_sc, float invh,
                                             float bas[4], int& c0) {
    float xn = x * inv_maxv_sc;
    xn = fminf(fmaxf(xn, -0.99f), 0.99f);
    float u = (xn + 1.0f) * invh;
    float fl = floorf(u);
    float t = u - fl;
    int fli = (int)fl;
    c0 = fli - 1;
    float omt = 1.0f - t;
    float t3 = t*t*t;
    float o3 = omt*omt*omt;
    bas[0] = (fli >= 1) ? o3 * (1.0f/6.0f) : 0.f;
    bas[1] = (2.0f-t)*(2.0f-t)*(2.0f-t)*(1.0f/6.0f) - o3*(4.0f/6.0f);
    bas[2] = (1.0f+t)*(1.0f+t)*(1.0f+t)*(1.0f/6.0f) - t3*(4.0f/6.0f);
    bas[3] = (fli <= 64) ? t3 * (1.0f/6.0f) : 0.f;
}

// ---------------- K2: spline -> act(fp16) + energy (f32x2 pairs over j, 1024 blocks) ----
#define SWST 12
__global__ void k_spline(const float* __restrict__ x_in,
                         const float* __restrict__ sw,
                         const float* __restrict__ omiga) {
    int bi = blockIdx.x, i = bi % IN_N, cy = blockIdx.y;
    __shared__ float s_swT[CC*SWST];
    __shared__ float s_om[JJ];
    __shared__ float s_red[8][9];
    __shared__ float s_pm;
    int tid = threadIdx.x;
    float maxv = reduce_maxv(tid, &s_pm) + 1e-8f;
    for (int t = tid; t < CC*JJ; t += blockDim.x) {
        int c = t >> 3, j = t & 7;
        s_swT[c*SWST + j] = sw[(i*JJ + j)*CC + c];
    }
    if (tid < JJ) s_om[tid] = fabsf(omiga[i*JJ + tid]);
    __syncthreads();

    float inv_maxv_sc = 0.95f / maxv;
    const float invh = (float)(CC - 1) * 0.5f;

    unsigned long long om2[4];
#pragma unroll
    for (int jj = 0; jj < 4; jj++) om2[jj] = packab(s_om[2*jj], s_om[2*jj + 1]);

    unsigned long long accp[4];
#pragma unroll
    for (int jj = 0; jj < 4; jj++) accp[jj] = 0ull;

    const float* xb   = x_in + (size_t)bi * SF;
    __half*      actb = g_act + (size_t)bi * JJ * SF;
    int p0 = (cy * ECHUNK) >> 1, p1 = min(SF, cy * ECHUNK + ECHUNK) >> 1;
    for (int p = p0 + tid; p < p1; p += blockDim.x) {
        int idx = 2 * p;
        float2 x2 = *(const float2*)(xb + idx);
        unsigned long long ap[4], aq[4];
        unsigned long long px = pack2(x2.x), py = pack2(x2.y);
#pragma unroll
        for (int jj = 0; jj < 4; jj++) { ap[jj] = 0ull; aq[jj] = 0ull; }
#pragma unroll
        for (int jj = 0; jj < 4; jj++) { ffma2(ap[jj], om2[jj], px); ffma2(aq[jj], om2[jj], py); }
        {
            float bas[4]; int c0;
            spline_basis(x2.x, inv_maxv_sc, invh, bas, c0);
            int r0[4] = { max(c0,0), c0+1, c0+2, min(c0+3, CC-1) };
#pragma unroll
            for (int k = 0; k < 4; k++) {
                const ulonglong2* pr = (const ulonglong2*)(s_swT + r0[k]*SWST);
                ulonglong2 lo = pr[0], hi = pr[1];
                unsigned long long bk = pack2(bas[k]);
                ffma2(ap[0], bk, lo.x); ffma2(ap[1], bk, lo.y);
                ffma2(ap[2], bk, hi.x); ffma2(ap[3], bk, hi.y);
            }
        }
        {
            float bas[4]; int c0;
            spline_basis(x2.y, inv_maxv_sc, invh, bas, c0);
            int r0[4] = { max(c0,0), c0+1, c0+2, min(c0+3, CC-1) };
#pragma unroll
            for (int k = 0; k < 4; k++) {
                const ulonglong2* pr = (const ulonglong2*)(s_swT + r0[k]*SWST);
                ulonglong2 lo = pr[0], hi = pr[1];
                unsigned long long bk = pack2(bas[k]);
                ffma2(aq[0], bk, lo.x); ffma2(aq[1], bk, lo.y);
                ffma2(aq[2], bk, hi.x); ffma2(aq[3], bk, hi.y);
            }
        }
#pragma unroll
        for (int jj = 0; jj < 4; jj++) {
            float e0lo, e0hi, e1lo, e1hi;
            unpack2(ap[jj], e0lo, e0hi);
            unpack2(aq[jj], e1lo, e1hi);
            *(__half2*)(actb + (size_t)(2*jj    )*SF + idx) = __floats2half2_rn(e0lo, e1lo);
            *(__half2*)(actb + (size_t)(2*jj + 1)*SF + idx) = __floats2half2_rn(e0hi, e1hi);
            ffma2(accp[jj], ap[jj], ap[jj]);
            ffma2(accp[jj], aq[jj], aq[jj]);
        }
    }
    float acc[JJ];
#pragma unroll
    for (int jj = 0; jj < 4; jj++) unpack2(accp[jj], acc[2*jj], acc[2*jj + 1]);
    int lane = tid & 31, wid = tid >> 5;
#pragma unroll
    for (int j = 0; j < JJ; j++) {
#pragma unroll
        for (int o = 16; o > 0; o >>= 1) acc[j] += __shfl_down_sync(0xffffffffu, acc[j], o);
        if (lane == 0) s_red[wid][j] = acc[j];
    }
    __syncthreads();
    if (tid < JJ) {
        float e = 0.f;
#pragma unroll
        for (int w = 0; w < 8; w++) e += s_red[w][tid];
        g_epart[(bi*NCHUNK + cy)*JJ + tid] = e;
    }
}

// ---------------- K3: fused combined + LN + W2 GEMV (3 rows per warp, 512 blocks) ----
__global__ void k_cxp(const float* __restrict__ W2,
                      const float* __restrict__ bparam,
                      const float* __restrict__ lnsc,
                      const float* __restrict__ lnbi,
                      const float* __restrict__ tau,
                      const float* __restrict__ temp,
                      float* __restrict__ xp_out) {
    int bj = blockIdx.x;
    int b = bj >> 3, j = bj & 7;
    __shared__ float W2s[FF*OO];
    __shared__ float s_sc[FF], s_bi[FF];
    __shared__ float s_mask[IN_N];
    __shared__ float xlnw[24][FF];
    int tid = threadIdx.x;

    for (int t = tid; t < FF*OO/4; t += blockDim.x)
        ((float4*)W2s)[t] = ((const float4*)(W2 + (size_t)j*FF*OO))[t];
    if (tid < FF) {
        s_sc[tid] = lnsc[j*FF + tid];
        s_bi[tid] = lnbi[j*FF + tid];
    }
    if (tid < IN_N) {
        int i = tid, bi = b*IN_N + i;
        float e = 0.f;
#pragma unroll
        for (int c = 0; c < NCHUNK; c++) e += g_epart[(bi*NCHUNK + c)*JJ + j];
        e *= (1.0f / (float)SF);
        float sq = sqrtf(e + 1e-8f);
        float ta = fabsf(tau[i*JJ + j]);
        float tv = fabsf(temp[0]) * sqrtf((float)SS / 256.0f) + 1e-4f;
        float mk = 1.0f / (1.0f + expf(-(sq - ta) / tv));
        s_mask[tid] = mk;
        if (blockIdx.y == 0) g_gate[bi*JJ + j] = (sq / (ta + 1e-8f)) * mk;
    }
    __syncthreads();

    int w = tid >> 5, lane = tid & 31;
    int s0 = blockIdx.y * 24;
    const float* bpj = bparam + (size_t)j*SS*OO;
    float* cmbb = g_comb + (size_t)bj*SF;
    float* xpb  = g_xp   + (size_t)bj*SS*OO;
    float* xob  = xp_out ? (xp_out + (size_t)bj*SS*OO) : nullptr;

    float m[8];
#pragma unroll
    for (int i = 0; i < 8; i++) m[i] = s_mask[i];

    int rbase = 3 * w;
#pragma unroll
    for (int r = 0; r < 3; r++) {
        int lr = rbase + r;
        int s = s0 + lr;
        if (s < SS) {
            float c0 = 0.f, c1 = 0.f;
#pragma unroll
            for (int i = 0; i < IN_N; i++) {
                const __half2* ap = (const __half2*)(g_act + ((size_t)(b*IN_N + i)*JJ + j)*SF
                                                     + (size_t)s*FF + 2*lane);
                float2 f2 = __half22float2(*ap);
                c0 += m[i] * f2.x;
                c1 += m[i] * f2.y;
            }
            *(float2*)(cmbb + (size_t)s*FF + 2*lane) = make_float2(c0, c1);
            float sm = c0 + c1, sq = c0*c0 + c1*c1;
#pragma unroll
            for (int o = 16; o > 0; o >>= 1) {
                sm += __shfl_xor_sync(0xffffffffu, sm, o);
                sq += __shfl_xor_sync(0xffffffffu, sq, o);
            }
            float mean = sm * (1.0f/64.0f);
            float var  = sq * (1.0f/64.0f) - mean*mean;
            float rstd = rsqrtf(var + 1e-5f);
            xlnw[lr][2*lane]     = (c0 - mean)*rstd*s_sc[2*lane]     + s_bi[2*lane];
            xlnw[lr][2*lane + 1] = (c1 - mean)*rstd*s_sc[2*lane + 1] + s_bi[2*lane + 1];
        } else {
            xlnw[lr][2*lane] = 0.f;
            xlnw[lr][2*lane + 1] = 0.f;
        }
    }
    __syncwarp();

    unsigned long long acc[3];
#pragma unroll
    for (int r = 0; r < 3; r++) {
        int s = s0 + rbase + r;
        acc[r] = (s < SS) ? *(const unsigned long long*)(bpj + (size_t)s*OO + 2*lane) : 0ull;
    }
#pragma unroll 8
    for (int ff = 0; ff < FF; ff++) {
        unsigned long long w2v = *(const unsigned long long*)&W2s[ff*OO + 2*lane];
        ffma2(acc[0], pack2(xlnw[rbase + 0][ff]), w2v);
        ffma2(acc[1], pack2(xlnw[rbase + 1][ff]), w2v);
        ffma2(acc[2], pack2(xlnw[rbase + 2][ff]), w2v);
    }
#pragma unroll
    for (int r = 0; r < 3; r++) {
        int s = s0 + rbase + r;
        if (s < SS) {
            *(unsigned long long*)(xpb + (size_t)s*OO + 2*lane) = acc[r];
            if (xob) *(unsigned long long*)(xob + (size_t)s*OO + 2*lane) = acc[r];
        }
    }
}

// ---------------- K4: P_m = projK @ projQ^T ----------------
__global__ void k_pgemm(const float* __restrict__ proj) {
    int bm = blockIdx.z;
    int b = bm >> 2, m = bm & 3;
    const float* A  = proj + ((size_t)(b*IN_N + 2*m    )*SS)*FF;
    const float* Bm = proj + ((size_t)(b*IN_N + 2*m + 1)*SS)*FF;
    float*       Cm = g_P + (size_t)bm*SS*SS;
    int m0 = blockIdx.y * 64, n0 = blockIdx.x * 64;

    __shared__ float As[16][64];
    __shared__ float Bs[16][64];
    int tid = threadIdx.x;
    int lr  = tid >> 2;
    int lc  = (tid & 3) * 4;
    int ty  = tid >> 4, tx = tid & 15;

    unsigned long long acc[4][2];
#pragma unroll
    for (int r = 0; r < 4; r++) { acc[r][0] = 0ull; acc[r][1] = 0ull; }

    for (int k0 = 0; k0 < FF; k0 += 16) {
        int row = m0 + lr;
        float4 va = (row < SS) ? *(const float4*)(A + (size_t)row*FF + k0 + lc)
                               : make_float4(0,0,0,0);
        As[lc+0][lr] = va.x; As[lc+1][lr] = va.y; As[lc+2][lr] = va.z; As[lc+3][lr] = va.w;
        int rowb = n0 + lr;
        float4 vb = (rowb < SS) ? *(const float4*)(Bm + (size_t)rowb*FF + k0 + lc)
                                : make_float4(0,0,0,0);
        Bs[lc+0][lr] = vb.x; Bs[lc+1][lr] = vb.y; Bs[lc+2][lr] = vb.z; Bs[lc+3][lr] = vb.w;
        __syncthreads();
#pragma unroll
        for (int k = 0; k < 16; k++) {
            float4 a4 = *(const float4*)&As[k][ty*4];
            ulonglong2 b2 = *(const ulonglong2*)&Bs[k][tx*4];
            unsigned long long p0 = pack2(a4.x), p1 = pack2(a4.y);
            unsigned long long p2 = pack2(a4.z), p3 = pack2(a4.w);
            ffma2(acc[0][0], p0, b2.x); ffma2(acc[0][1], p0, b2.y);
            ffma2(acc[1][0], p1, b2.x); ffma2(acc[1][1], p1, b2.y);
            ffma2(acc[2][0], p2, b2.x); ffma2(acc[2][1], p2, b2.y);
            ffma2(acc[3][0], p3, b2.x); ffma2(acc[3][1], p3, b2.y);
        }
        __syncthreads();
    }
#pragma unroll
    for (int r = 0; r < 4; r++) {
        int sRow = m0 + ty*4 + r;
        if (sRow >= SS) continue;
        float c0, c1, c2, c3;
        unpack2(acc[r][0], c0, c1);
        unpack2(acc[r][1], c2, c3);
        int tCol = n0 + tx*4;
        float* dst = Cm + (size_t)sRow*SS + tCol;
        if (tCol + 3 < SS) { dst[0]=c0; dst[1]=c1; dst[2]=c2; dst[3]=c3; }
        else {
            if (tCol+0 < SS) dst[0]=c0;
            if (tCol+1 < SS) dst[1]=c1;
            if (tCol+2 < SS) dst[2]=c2;
            if (tCol+3 < SS) dst[3]=c3;
        }
    }
}

// ---------------- K5: fused raw-reconstruct + softmax + attn GEMM + conv + residual ----
#define AST_LD 65
__global__ void k_attn(const float* __restrict__ w3,
                       const float* __restrict__ alpha,
                       const float* __restrict__ beta,
                       const float* __restrict__ theta,
                       const float* __restrict__ gamma,
                       const float* __restrict__ temp,
                       float* __restrict__ outp) {
    extern __shared__ float smem[];
    float* Ast = smem;
    float* Bxs = Ast + 192*AST_LD;
    float* w3s = Bxs + 192*64;
    __shared__ float qr_sh[SS], qmr_sh[SS];
    __shared__ float km_sh[64], As_sh[64];
    __shared__ float a_sh[4];

    int bj = blockIdx.y;
    int j  = bj & 7, b = bj >> 3;
    int m0 = blockIdx.x * 64;
    int tid = threadIdx.x;

    const float* Bx = g_xp  + (size_t)bj*SS*OO;
    const float* Cb = g_comb + (size_t)bj*SS*FF;
    float*       Ob = outp + (size_t)bj*SS*OO;

    float tv = fabsf(temp[0]) * sqrtf((float)SS / 256.0f) + 1e-4f;
    float inv_scale = 1.0f / (16.0f * tv);

    for (int t = tid; t < SS*OO/4; t += 256)
        ((float4*)Bxs)[t] = ((const float4*)Bx)[t];
    for (int t = SS*OO + tid; t < 192*64; t += 256) Bxs[t] = 0.f;
    for (int t = tid; t < OO*KK; t += 256) w3s[t] = w3[(size_t)j*OO*KK + t];

    if (tid < 4) {
        float gK = g_gate[(b*IN_N + 2*tid    )*JJ + j];
        float gQ = g_gate[(b*IN_N + 2*tid + 1)*JJ + j];
        a_sh[tid] = gK * gQ;
    }
    if (tid < SS) {
        float qm = 0.f, qs = 0.f;
#pragma unroll
        for (int m = 0; m < 4; m++) {
            int bi = b*IN_N + 2*m + 1;
            float g = g_gate[bi*JJ + j];
            qm += g * g_rs[bi*SS + tid];
            qs += g * g * g_ss[bi*SS + tid];
        }
        qm *= (1.0f/256.0f); qs *= (1.0f/256.0f);
        float qr = rsqrtf(qs - qm*qm + 1e-5f);
        qr_sh[tid]  = qr;
        qmr_sh[tid] = 256.0f * qm * qr;
    }
    if (tid >= 192) {
        int r = tid - 192;
        int s = m0 + r;
        if (s < SS) {
            float km = 0.f, ks = 0.f;
#pragma unroll
            for (int m = 0; m < 4; m++) {
                int bi = b*IN_N + 2*m;
                float g = g_gate[bi*JJ + j];
                km += g * g_rs[bi*SS + s];
                ks += g * g * g_ss[bi*SS + s];
            }
            km *= (1.0f/256.0f); ks *= (1.0f/256.0f);
            float kr = rsqrtf(ks - km*km + 1e-5f);
            km_sh[r] = km;
            As_sh[r] = inv_scale * kr;
        }
    }
    __syncthreads();

    float a0 = a_sh[0], a1 = a_sh[1], a2 = a_sh[2], a3 = a_sh[3];
    const float* Pb = g_P + (size_t)(b*4)*SS*SS;

    int w = tid >> 5, lane = tid & 31;
    for (int r = w; r < 64; r += 8) {
        int s = m0 + r;
        if (s < SS) {
            float km = km_sh[r], Asc = As_sh[r];
            const float* P0 = Pb + (size_t)0*SS*SS + (size_t)s*SS;
            const float* P1 = Pb + (size_t)1*SS*SS + (size_t)s*SS;
            const float* P2 = Pb + (size_t)2*SS*SS + (size_t)s*SS;
            const float* P3 = Pb + (size_t)3*SS*SS + (size_t)s*SS;
            float v[6];
            float mx = -3.0e38f;
#pragma unroll
            for (int u = 0; u < 6; u++) {
                int t = lane + 32*u;
                if (t < SS) {
                    float G = a0*P0[t] + a1*P1[t] + a2*P2[t] + a3*P3[t];
                    v[u] = Asc * (qr_sh[t]*G - km*qmr_sh[t]);
                } else v[u] = -3.0e38f;
                mx = fmaxf(mx, v[u]);
            }
#pragma unroll
            for (int o = 16; o > 0; o >>= 1) mx = fmaxf(mx, __shfl_xor_sync(0xffffffffu, mx, o));
            float sum = 0.f;
#pragma unroll
            for (int u = 0; u < 6; u++) {
                int t = lane + 32*u;
                v[u] = (t < SS) ? expf(v[u] - mx) : 0.f;
                sum += v[u];
            }
#pragma unroll
            for (int o = 16; o > 0; o >>= 1) sum += __shfl_xor_sync(0xffffffffu, sum, o);
            float inv = 1.0f / sum;
#pragma unroll
            for (int u = 0; u < 6; u++) Ast[(lane + 32*u)*AST_LD + r] = v[u] * inv;
        } else {
#pragma unroll
            for (int u = 0; u < 6; u++) Ast[(lane + 32*u)*AST_LD + r] = 0.f;
        }
    }
    __syncthreads();

    int ty = tid >> 4, tx = tid & 15;
    unsigned long long acc[4][2];
#pragma unroll
    for (int r = 0; r < 4; r++) { acc[r][0] = 0ull; acc[r][1] = 0ull; }

#pragma unroll 4
    for (int k = 0; k < 192; k++) {
        const float* ap = Ast + k*AST_LD + ty*4;
        float b0 = ap[0], b1 = ap[1], b2v = ap[2], b3 = ap[3];
        ulonglong2 bp = *(const ulonglong2*)(Bxs + k*64 + tx*4);
        unsigned long long p0 = pack2(b0), p1 = pack2(b1);
        unsigned long long p2 = pack2(b2v), p3 = pack2(b3);
        ffma2(acc[0][0], p0, bp.x); ffma2(acc[0][1], p0, bp.y);
        ffma2(acc[1][0], p1, bp.x); ffma2(acc[1][1], p1, bp.y);
        ffma2(acc[2][0], p2, bp.x); ffma2(acc[2][1], p2, bp.y);
        ffma2(acc[3][0], p3, bp.x); ffma2(acc[3][1], p3, bp.y);
    }

    float al = fabsf(alpha[j]), be = fabsf(beta[j]);
    float th = fabsf(theta[j]), ga = gamma[j];

    float outv[4][4];
#pragma unroll
    for (int c = 0; c < 4; c++) {
        int o = tx*4 + c;
        float w3v[KK];
#pragma unroll
        for (int k = 0; k < KK; k++) w3v[k] = w3s[o*KK + k];
        float xv[18];
        int base = m0 + ty*4 - 7;
#pragma unroll
        for (int t = 0; t < 18; t++) {
            int si = base + t;
            xv[t] = (si >= 0 && si < 192) ? Bxs[si*64 + o] : 0.f;
        }
#pragma unroll
        for (int r = 0; r < 4; r++) {
            float cv = 0.f;
#pragma unroll
            for (int k = 0; k < KK; k++) cv += xv[r + k] * w3v[k];
            float glo, ghi;
            unpack2(acc[r][c >> 1], glo, ghi);
            float gval = (c & 1) ? ghi : glo;
            outv[r][c] = be*gval + al*xv[r + 7] + th*cv;
        }
    }
#pragma unroll
    for (int r = 0; r < 4; r++) {
        int s = m0 + ty*4 + r;
        if (s >= SS) continue;
#pragma unroll
        for (int c = 0; c < 4; c++) {
            int o = tx*4 + c;
            Ob[(size_t)s*OO + o] = outv[r][c] + ga*Cb[(size_t)s*FF + o];
        }
    }
}

// ---------------- launch ----------------
extern "C" void kernel_launch(void* const* d_in, const int* in_sizes, int n_in,
                              void* d_out, int out_size) {
    const float* x_in   = (const float*)d_in[0];
    const float* proj   = (const float*)d_in[1];
    const float* sw     = (const float*)d_in[2];
    const float* tau    = (const float*)d_in[3];
    const float* temp   = (const float*)d_in[4];
    const float* omiga  = (const float*)d_in[5];
    const float* W2     = (const float*)d_in[6];
    const float* bparam = (const float*)d_in[7];
    const float* lnsc   = (const float*)d_in[8];
    const float* lnbi   = (const float*)d_in[9];
    const float* alpha  = (const float*)d_in[10];
    const float* beta   = (const float*)d_in[11];
    const float* theta  = (const float*)d_in[12];
    const float* gamma  = (const float*)d_in[13];
    const float* w3     = (const float*)d_in[14];
    float* outp = (float*)d_out;
    float* xp_out = (out_size >= 2 * NOUT) ? (outp + NOUT) : nullptr;

    static cudaStream_t s2 = nullptr;
    static cudaEvent_t evA = nullptr, evB = nullptr;
    if (!s2) {
        cudaStreamCreateWithFlags(&s2, cudaStreamNonBlocking);
        cudaEventCreateWithFlags(&evA, cudaEventDisableTiming);
        cudaEventCreateWithFlags(&evB, cudaEventDisableTiming);
    }

    const int attn_smem = (192*AST_LD + 192*64 + OO*KK) * sizeof(float);
    cudaFuncSetAttribute(k_attn, cudaFuncAttributeMaxDynamicSharedMemorySize, attn_smem);

    cudaEventRecord(evA, 0);
    cudaStreamWaitEvent(s2, evA, 0);
    k_pgemm<<<dim3(3, 3, BB*4), 256, 0, s2>>>(proj);
    cudaEventRecord(evB, s2);

    k_prep  <<<148 + BB*IN_N, 256>>>(x_in, BB*IN_N*SS*FF, proj);
    k_spline<<<dim3(BB*IN_N, NCHUNK), 256>>>(x_in, sw, omiga);
    k_cxp   <<<dim3(BB*JJ, 8), 256>>>(W2, bparam, lnsc, lnbi, tau, temp, xp_out);

    cudaStreamWaitEvent(0, evB, 0);
    k_attn  <<<dim3(3, BB*JJ), 256, attn_smem>>>(w3, alpha, beta, theta, gamma, temp, outp);
}